// round 1
// baseline (speedup 1.0000x reference)
#include <cuda_runtime.h>
#include <cuda_fp16.h>

#define N      4096
#define NB     128     // persistent blocks (<= SM count -> co-resident wave 1)
#define NT     256
#define RPB    32      // rows per block (NB * RPB == N)
#define NITER  64

// ---- persistent device scratch (module globals; no runtime allocation) ----
__device__ __align__(16) __half g_Kh [(size_t)N * N];   // K = k*k, row-major, fp16 (32 MB)
__device__ __align__(16) __half g_KhT[(size_t)N * N];   // K^T row-major, fp16       (32 MB)
__device__ __align__(16) float  g_AF[N];
__device__ __align__(16) float  g_BF[N];
__device__ unsigned int g_bar;

// ---- grid-wide barrier: monotone counter, reset per launch by reset_bar ----
__device__ __forceinline__ void grid_sync(unsigned int target) {
    __syncthreads();
    if (threadIdx.x == 0) {
        __threadfence();                    // release: publish our stores to L2
        atomicAdd(&g_bar, 1u);
        while (*((volatile unsigned int*)&g_bar) < target) { }
        __threadfence();                    // acquire-ish
    }
    __syncthreads();
}

__global__ void reset_bar_kernel() { g_bar = 0u; }

// ---- stage a 4096-float vector from L2 (bypass L1) into shared memory ----
__device__ __forceinline__ void load_vec_smem(float* s_vec, const float* g_src, int tid) {
    const float4* src4 = (const float4*)g_src;
    float4*       dst4 = (float4*)s_vec;
#pragma unroll
    for (int q = 0; q < (N / 4) / NT; ++q)          // 1024 float4 / 256 thr = 4
        dst4[tid + q * NT] = __ldcg(src4 + tid + q * NT);
}

// ---- one strip matvec: rows [rbase, rbase+RPB) of M (fp16) dotted with s_vec,
//      out[row] = scal[row](^2) / (1 + dot). 4 rows per warp, half8 loads. ----
template <bool SQUARE>
__device__ __forceinline__ void matvec_strip(const __half* __restrict__ M,
                                             const float*  __restrict__ s_vec,
                                             int rbase,
                                             const float* __restrict__ scal,
                                             float* __restrict__ outv)
{
    const int tid  = threadIdx.x;
    const int w    = tid >> 5;
    const int lane = tid & 31;
    const int r0   = rbase + (w << 2);              // 8 warps * 4 rows = 32 rows
    const __half*  row = M + (size_t)r0 * N;
    const float4*  sv4 = (const float4*)s_vec;

    float acc[4] = {0.f, 0.f, 0.f, 0.f};
#pragma unroll 4
    for (int s = 0; s < 16; ++s) {
        const int i = s * 256 + lane * 8;           // 8 elements per lane per step
        const float4 v0 = sv4[(i >> 2)];
        const float4 v1 = sv4[(i >> 2) + 1];
#pragma unroll
        for (int r = 0; r < 4; ++r) {
            float4 kr = *(const float4*)(row + (size_t)r * N + i);   // 8 halfs
            const __half2* h = (const __half2*)&kr;
            const float2 f0 = __half22float2(h[0]);
            const float2 f1 = __half22float2(h[1]);
            const float2 f2 = __half22float2(h[2]);
            const float2 f3 = __half22float2(h[3]);
            acc[r] += f0.x * v0.x + f0.y * v0.y + f1.x * v0.z + f1.y * v0.w
                    + f2.x * v1.x + f2.y * v1.y + f3.x * v1.z + f3.y * v1.w;
        }
    }
#pragma unroll
    for (int r = 0; r < 4; ++r) {
        float a = acc[r];
#pragma unroll
        for (int off = 16; off; off >>= 1)
            a += __shfl_xor_sync(0xffffffffu, a, off);
        if (lane == r) {
            const int rowi = r0 + r;
            float sc = scal[rowi];
            if (SQUARE) sc *= sc;
            __stcg(outv + rowi, sc / (1.0f + a));
        }
    }
}

__global__ void __launch_bounds__(NT, 1)
competitive_kernel(const float* __restrict__ AT, const float* __restrict__ k,
                   const float* __restrict__ bt, float* __restrict__ C)
{
    __shared__ float s_vec[N];           // 16 KB: AF or BF staged per phase
    __shared__ float s_tile[32][33];     // phase-0 transpose tile / reused as s_af

    const int tid  = threadIdx.x;
    const int b    = blockIdx.x;
    const int i0   = b * RPB;
    const int w    = tid >> 5;
    const int lane = tid & 31;

    // ---------- phase 0: Kh = fp16(k*k); KhT = transpose; init AF = AT ----------
    for (int t = 0; t < N / 32; ++t) {
        const int j0 = t * 32;
#pragma unroll
        for (int rr = 0; rr < 4; ++rr) {
            const int r = rr * 8 + w;
            float v = k[(size_t)(i0 + r) * N + j0 + lane];
            v *= v;
            g_Kh[(size_t)(i0 + r) * N + j0 + lane] = __float2half(v);
            s_tile[lane][r] = v;                     // transposed store, conflict-free
        }
        __syncthreads();
#pragma unroll
        for (int rr = 0; rr < 4; ++rr) {
            const int r = rr * 8 + w;                // local j index
            g_KhT[(size_t)(j0 + r) * N + i0 + lane] = __float2half(s_tile[r][lane]);
        }
        __syncthreads();
    }
    if (tid < RPB) __stcg(&g_AF[i0 + tid], AT[i0 + tid]);

    unsigned int tgt = 0;
    grid_sync(tgt += NB);

    // ---------- 64 fixed-point iterations ----------
    for (int it = 0; it < NITER; ++it) {
        // BF = bt^2 / (1 + K^T @ AF)   -- strip of KhT rows (= K columns)
        load_vec_smem(s_vec, g_AF, tid);
        __syncthreads();
        matvec_strip<true >(g_KhT, s_vec, i0, bt, g_BF);
        grid_sync(tgt += NB);

        // AF = AT / (1 + K @ BF)       -- strip of Kh rows
        load_vec_smem(s_vec, g_BF, tid);
        __syncthreads();
        matvec_strip<false>(g_Kh, s_vec, i0, AT, g_AF);
        grid_sync(tgt += NB);
    }

    // ---------- output: C[i][j] = AF_i * k_ij^2 * BF_j  (fp32 k for accuracy) ----------
    load_vec_smem(s_vec, g_BF, tid);                 // BF full vector
    float* s_af = &s_tile[0][0];
    if (tid < RPB) s_af[tid] = __ldcg(&g_AF[i0 + tid]);
    __syncthreads();

    const int r0 = (w << 2);
    float af[4];
#pragma unroll
    for (int r = 0; r < 4; ++r) af[r] = s_af[r0 + r];
    const float4* sv4 = (const float4*)s_vec;

    for (int s = 0; s < 32; ++s) {
        const int j = s * 128 + lane * 4;
        const float4 bv = sv4[j >> 2];
#pragma unroll
        for (int r = 0; r < 4; ++r) {
            const size_t off = (size_t)(i0 + r0 + r) * N + j;
            const float4 kv = *(const float4*)(k + off);
            float4 c;
            c.x = af[r] * kv.x * kv.x * bv.x;
            c.y = af[r] * kv.y * kv.y * bv.y;
            c.z = af[r] * kv.z * kv.z * bv.z;
            c.w = af[r] * kv.w * kv.w * bv.w;
            *(float4*)(C + off) = c;
        }
    }
}

extern "C" void kernel_launch(void* const* d_in, const int* in_sizes, int n_in,
                              void* d_out, int out_size) {
    const float* AT = (const float*)d_in[0];
    const float* k  = (const float*)d_in[1];
    const float* bt = (const float*)d_in[2];
    float* C = (float*)d_out;

    reset_bar_kernel<<<1, 1>>>();                       // deterministic per-launch barrier reset
    competitive_kernel<<<NB, NT>>>(AT, k, bt, C);
}

// round 2
// speedup vs baseline: 1.1384x; 1.1384x over previous
#include <cuda_runtime.h>
#include <cuda_fp16.h>

#define N        4096
#define NB       128     // persistent blocks, 1 per SM (co-resident wave 1)
#define NT       1024
#define RPB      32      // rows per block
#define NITER    64
#define CA_GROUPS 3      // row-groups (4 rows each) pinned in L1 via .ca: 12 rows * 8KB * 2 = 192KB

// ---- persistent device scratch ----
__device__ __align__(16) __half g_Kh [(size_t)N * N];   // K = k*k row-major fp16 (32 MB)
__device__ __align__(16) __half g_KhT[(size_t)N * N];   // K^T row-major fp16      (32 MB)
__device__ __align__(16) float  g_AF[N];
__device__ __align__(16) float  g_BF[N];
__device__ unsigned int g_bar;

__global__ void reset_bar_kernel() { g_bar = 0u; }

__device__ __forceinline__ void grid_sync(unsigned int target) {
    __syncthreads();
    if (threadIdx.x == 0) {
        __threadfence();                    // release our L2 stores
        atomicAdd(&g_bar, 1u);
        while (*((volatile unsigned int*)&g_bar) < target) { }
        __threadfence();
    }
    __syncthreads();
}

// stage 4096-float vector from L2 (bypass L1) into SMEM: 1 float4 per thread
__device__ __forceinline__ void load_vec_smem(float* s_vec, const float* g_src, int tid) {
    ((float4*)s_vec)[tid] = __ldcg((const float4*)g_src + tid);
}

// Warp-partial dot: 4 rows (group g), 1024-column segment (quarter q).
// Writes 4 partial sums to s_part[(g*4+r)*4 + q] from lane 0.
template <bool CA>
__device__ __forceinline__ void phase_dot(const __half* __restrict__ M,
                                          const float*  __restrict__ s_vec,
                                          int i0, int g, int q, int lane,
                                          float* __restrict__ s_part)
{
    const int c0 = q << 10;                 // column base
    const int r0 = g << 2;                  // local row base
    const __half* Mrow = M + (size_t)(i0 + r0) * N + c0;
    const float4* sv4  = (const float4*)(s_vec + c0);

    float acc[4] = {0.f, 0.f, 0.f, 0.f};
#pragma unroll
    for (int s = 0; s < 4; ++s) {
        const int i = (s << 8) + (lane << 3);       // 8 halfs per lane per step
        const float4 v0 = sv4[(i >> 2)];
        const float4 v1 = sv4[(i >> 2) + 1];
#pragma unroll
        for (int r = 0; r < 4; ++r) {
            const float4* p = (const float4*)(Mrow + (size_t)r * N + i);
            const float4 kr = CA ? __ldca(p) : __ldcg(p);
            const __half2* h = (const __half2*)&kr;
            const float2 f0 = __half22float2(h[0]);
            const float2 f1 = __half22float2(h[1]);
            const float2 f2 = __half22float2(h[2]);
            const float2 f3 = __half22float2(h[3]);
            acc[r] += f0.x * v0.x + f0.y * v0.y + f1.x * v0.z + f1.y * v0.w
                    + f2.x * v1.x + f2.y * v1.y + f3.x * v1.z + f3.y * v1.w;
        }
    }
#pragma unroll
    for (int r = 0; r < 4; ++r) {
        float a = acc[r];
#pragma unroll
        for (int off = 16; off; off >>= 1)
            a += __shfl_xor_sync(0xffffffffu, a, off);
        if (lane == 0) s_part[((r0 + r) << 2) + q] = a;
    }
}

__global__ void __launch_bounds__(NT, 1)
competitive_kernel(const float* __restrict__ AT, const float* __restrict__ k,
                   const float* __restrict__ bt, float* __restrict__ C)
{
    __shared__ float s_vec[N];              // 16 KB
    __shared__ float s_tile[64][33];        // 8.4 KB (phase-0 transpose)
    __shared__ float s_part[RPB * 4];       // partial dots
    __shared__ float s_af[RPB];

    const int tid  = threadIdx.x;
    const int w    = tid >> 5;              // 0..31
    const int lane = tid & 31;
    const int g    = w >> 2;                // row group 0..7
    const int q    = w & 3;                 // column quarter 0..3
    const int i0   = blockIdx.x * RPB;

    // per-row scalars held in registers by the first 32 threads
    float r_at = 0.f, r_bt2 = 0.f;
    if (tid < RPB) {
        r_at  = AT[i0 + tid];
        float b = bt[i0 + tid];
        r_bt2 = b * b;
    }

    // ---------- phase 0: Kh = fp16(k*k), KhT = transpose, AF = AT ----------
    for (int t = 0; t < N / 64; ++t) {
        const int j0 = t * 64;
        const size_t roff = (size_t)(i0 + w) * N + j0;
        float2 v = __ldcs((const float2*)(k + roff) + lane);
        v.x *= v.x; v.y *= v.y;
        *(__half2*)(g_Kh + roff + lane * 2) = __floats2half2_rn(v.x, v.y);
        s_tile[lane * 2    ][w] = v.x;
        s_tile[lane * 2 + 1][w] = v.y;
        __syncthreads();
#pragma unroll
        for (int qq = 0; qq < 2; ++qq) {
            const int c = w * 2 + qq;       // tile-local column
            g_KhT[(size_t)(j0 + c) * N + i0 + lane] = __float2half(s_tile[c][lane]);
        }
        __syncthreads();
    }
    if (tid < RPB) __stcg(&g_AF[i0 + tid], r_at);

    unsigned int tgt = 0;
    grid_sync(tgt += NB);

    // ---------- 64 fixed-point iterations ----------
    for (int it = 0; it < NITER; ++it) {
        // BF = bt^2 / (1 + K^T @ AF)
        load_vec_smem(s_vec, g_AF, tid);
        __syncthreads();
        if (g < CA_GROUPS) phase_dot<true >(g_KhT, s_vec, i0, g, q, lane, s_part);
        else               phase_dot<false>(g_KhT, s_vec, i0, g, q, lane, s_part);
        __syncthreads();
        if (tid < RPB) {
            const float a = s_part[tid * 4] + s_part[tid * 4 + 1]
                          + s_part[tid * 4 + 2] + s_part[tid * 4 + 3];
            __stcg(&g_BF[i0 + tid], r_bt2 / (1.0f + a));
        }
        grid_sync(tgt += NB);

        // AF = AT / (1 + K @ BF)
        load_vec_smem(s_vec, g_BF, tid);
        __syncthreads();
        if (g < CA_GROUPS) phase_dot<true >(g_Kh, s_vec, i0, g, q, lane, s_part);
        else               phase_dot<false>(g_Kh, s_vec, i0, g, q, lane, s_part);
        __syncthreads();
        if (tid < RPB) {
            const float a = s_part[tid * 4] + s_part[tid * 4 + 1]
                          + s_part[tid * 4 + 2] + s_part[tid * 4 + 3];
            __stcg(&g_AF[i0 + tid], r_at / (1.0f + a));
        }
        grid_sync(tgt += NB);
    }

    // ---------- output: C[i][j] = AF_i * k_ij^2 * BF_j  (fp32 k) ----------
    load_vec_smem(s_vec, g_BF, tid);        // BF
    if (tid < RPB) s_af[tid] = __ldcg(&g_AF[i0 + tid]);
    __syncthreads();

    const float af = s_af[w];               // warp w -> row i0 + w
    const float4* sv4 = (const float4*)s_vec;
#pragma unroll 4
    for (int s = 0; s < 32; ++s) {
        const int j = s * 128 + lane * 4;
        const size_t off = (size_t)(i0 + w) * N + j;
        const float4 kv = __ldcs((const float4*)(k + off));
        const float4 bv = sv4[j >> 2];
        float4 c4;
        c4.x = af * kv.x * kv.x * bv.x;
        c4.y = af * kv.y * kv.y * bv.y;
        c4.z = af * kv.z * kv.z * bv.z;
        c4.w = af * kv.w * kv.w * bv.w;
        *(float4*)(C + off) = c4;
    }
}

extern "C" void kernel_launch(void* const* d_in, const int* in_sizes, int n_in,
                              void* d_out, int out_size) {
    const float* AT = (const float*)d_in[0];
    const float* k  = (const float*)d_in[1];
    const float* bt = (const float*)d_in[2];
    float* C = (float*)d_out;

    reset_bar_kernel<<<1, 1>>>();
    competitive_kernel<<<NB, NT>>>(AT, k, bt, C);
}

// round 3
// speedup vs baseline: 2.4728x; 2.1722x over previous
#include <cuda_runtime.h>
#include <cuda_fp16.h>

#define N       4096
#define NB      128     // persistent blocks, 1/SM, co-resident wave 1
#define NT      1024
#define RPB     32      // rows per block
#define NIT8    30      // fp8 (e4m3) iterations
#define NIT16   8       // fp16 refinement iterations

// ---- persistent device scratch ----
__device__ __align__(16) __half        g_Kh [(size_t)N * N];   // K fp16 row-major  (32 MB)
__device__ __align__(16) __half        g_KhT[(size_t)N * N];   // K^T fp16          (32 MB)
__device__ __align__(16) unsigned char g_K8 [(size_t)N * N];   // K e4m3            (16 MB)
__device__ __align__(16) unsigned char g_K8T[(size_t)N * N];   // K^T e4m3          (16 MB)
__device__ __align__(16) float g_AF[N];
__device__ __align__(16) float g_BF[N];
__device__ unsigned int g_bar;

__global__ void reset_bar_kernel() { g_bar = 0u; }

// ---- fence-free grid barrier: bar.sync + cumulative release-red + L2 poll.
//      NO gpu-scope fence => NO CCTL.IVALL => L1-pinned K lines survive. ----
__device__ __forceinline__ void grid_sync(unsigned target) {
    __syncthreads();
    if (threadIdx.x == 0) {
        asm volatile("red.release.gpu.global.add.u32 [%0], %1;"
                     :: "l"(&g_bar), "r"(1u) : "memory");
        unsigned v;
        do {
            asm volatile("ld.global.cg.u32 %0, [%1];" : "=r"(v) : "l"(&g_bar) : "memory");
        } while (v < target);
    }
    __syncthreads();
}

// ---- fp8 helpers ----
__device__ __forceinline__ unsigned short h2_to_e4m3x2(unsigned h2bits) {
    unsigned short r;
    asm("cvt.rn.satfinite.e4m3x2.f16x2 %0, %1;" : "=h"(r) : "r"(h2bits));
    return r;
}
__device__ __forceinline__ __half2 e4m3x2_to_h2(unsigned short u) {
    unsigned r;
    asm("cvt.rn.f16x2.e4m3x2 %0, %1;" : "=r"(r) : "h"(u));
    return *reinterpret_cast<__half2*>(&r);
}

// ---- stage vectors into SMEM (always via L2; AF/BF are mutable) ----
__device__ __forceinline__ void load_vec_f(float* s_vec, const float* g_src, int tid) {
    ((float4*)s_vec)[tid] = __ldcg((const float4*)g_src + tid);
}
__device__ __forceinline__ void load_vec_h(__half2* s_vh, const float* g_src, int tid) {
    float4 v = __ldcg((const float4*)g_src + tid);
    s_vh[2 * tid]     = __floats2half2_rn(v.x, v.y);
    s_vh[2 * tid + 1] = __floats2half2_rn(v.z, v.w);
}

// ---- fp8 strip dot: group g owns 4 rows, quarter q owns 1024 cols.
//      16 fp8/lane/step, HFMA2 chunk accum -> float. CA pins strip in L1. ----
template <bool CA>
__device__ __forceinline__ void dot8(const unsigned char* __restrict__ M,
                                     const __half2* __restrict__ s_vh,
                                     int i0, int g, int q, int lane,
                                     float* __restrict__ s_part)
{
    const int c0 = q << 10;
    const int r0 = g << 2;
    const unsigned char* Mp = M + (size_t)(i0 + r0) * N + c0;
    const uint4* vh4 = (const uint4*)(s_vh + (c0 >> 1));     // 8 halves per uint4

    float acc[4] = {0.f, 0.f, 0.f, 0.f};
#pragma unroll
    for (int s = 0; s < 2; ++s) {
        const int e0 = (s << 9) + (lane << 4);                // 16 elems per lane
        uint4 va = vh4[(e0 >> 3)];
        uint4 vb = vh4[(e0 >> 3) + 1];
        const __half2* vha = (const __half2*)&va;
        const __half2* vhb = (const __half2*)&vb;
#pragma unroll
        for (int r = 0; r < 4; ++r) {
            const uint4* p = (const uint4*)(Mp + (size_t)r * N + e0);
            uint4 kd = CA ? __ldca(p) : __ldcg(p);
            __half2 a2 = __floats2half2_rn(0.f, 0.f);
            a2 = __hfma2(e4m3x2_to_h2((unsigned short)kd.x),         vha[0], a2);
            a2 = __hfma2(e4m3x2_to_h2((unsigned short)(kd.x >> 16)), vha[1], a2);
            a2 = __hfma2(e4m3x2_to_h2((unsigned short)kd.y),         vha[2], a2);
            a2 = __hfma2(e4m3x2_to_h2((unsigned short)(kd.y >> 16)), vha[3], a2);
            a2 = __hfma2(e4m3x2_to_h2((unsigned short)kd.z),         vhb[0], a2);
            a2 = __hfma2(e4m3x2_to_h2((unsigned short)(kd.z >> 16)), vhb[1], a2);
            a2 = __hfma2(e4m3x2_to_h2((unsigned short)kd.w),         vhb[2], a2);
            a2 = __hfma2(e4m3x2_to_h2((unsigned short)(kd.w >> 16)), vhb[3], a2);
            float2 f = __half22float2(a2);
            acc[r] += f.x + f.y;
        }
    }
#pragma unroll
    for (int r = 0; r < 4; ++r) {
        float a = acc[r];
#pragma unroll
        for (int off = 16; off; off >>= 1) a += __shfl_xor_sync(0xffffffffu, a, off);
        if (lane == 0) s_part[((r0 + r) << 2) + q] = a;
    }
}

// ---- fp16 strip dot (fp32 vector + fp32 accum) for refinement iterations ----
__device__ __forceinline__ void dot16(const __half* __restrict__ M,
                                      const float*  __restrict__ s_vec,
                                      int i0, int g, int q, int lane,
                                      float* __restrict__ s_part)
{
    const int c0 = q << 10;
    const int r0 = g << 2;
    const __half* Mp = M + (size_t)(i0 + r0) * N + c0;
    const float4* sv4 = (const float4*)(s_vec + c0);

    float acc[4] = {0.f, 0.f, 0.f, 0.f};
#pragma unroll
    for (int s = 0; s < 4; ++s) {
        const int i = (s << 8) + (lane << 3);
        const float4 v0 = sv4[(i >> 2)];
        const float4 v1 = sv4[(i >> 2) + 1];
#pragma unroll
        for (int r = 0; r < 4; ++r) {
            const float4 kr = __ldcg((const float4*)(Mp + (size_t)r * N + i));
            const __half2* h = (const __half2*)&kr;
            const float2 f0 = __half22float2(h[0]);
            const float2 f1 = __half22float2(h[1]);
            const float2 f2 = __half22float2(h[2]);
            const float2 f3 = __half22float2(h[3]);
            acc[r] += f0.x * v0.x + f0.y * v0.y + f1.x * v0.z + f1.y * v0.w
                    + f2.x * v1.x + f2.y * v1.y + f3.x * v1.z + f3.y * v1.w;
        }
    }
#pragma unroll
    for (int r = 0; r < 4; ++r) {
        float a = acc[r];
#pragma unroll
        for (int off = 16; off; off >>= 1) a += __shfl_xor_sync(0xffffffffu, a, off);
        if (lane == 0) s_part[((r0 + r) << 2) + q] = a;
    }
}

__global__ void __launch_bounds__(NT, 1)
competitive_kernel(const float* __restrict__ AT, const float* __restrict__ k,
                   const float* __restrict__ bt, float* __restrict__ C)
{
    __shared__ float   s_vec[N];            // 16 KB fp32 vector (aliased as transpose tile)
    __shared__ __half2 s_vh[N / 2];         // 8 KB fp16 vector
    __shared__ float   s_part[RPB * 4];
    __shared__ float   s_af[RPB];

    const int tid  = threadIdx.x;
    const int w    = tid >> 5;
    const int lane = tid & 31;
    const int g    = w >> 2;                // row group 0..7
    const int q    = w & 3;                 // column quarter 0..3
    const int i0   = blockIdx.x * RPB;

    float r_at = 0.f, r_bt2 = 0.f;
    if (tid < RPB) {
        r_at = AT[i0 + tid];
        float b = bt[i0 + tid];
        r_bt2 = b * b;
    }

    // ---------- phase 0a: Kh = fp16(k*k), KhT = transpose, AF = AT ----------
    {
        float (*s_tile)[33] = (float(*)[33])s_vec;      // 64*33*4 = 8.4 KB < 16 KB
        for (int t = 0; t < N / 64; ++t) {
            const int j0 = t * 64;
            const size_t roff = (size_t)(i0 + w) * N + j0;
            float2 v = __ldcs((const float2*)(k + roff) + lane);
            v.x *= v.x; v.y *= v.y;
            *(__half2*)(g_Kh + roff + lane * 2) = __floats2half2_rn(v.x, v.y);
            s_tile[lane * 2    ][w] = v.x;
            s_tile[lane * 2 + 1][w] = v.y;
            __syncthreads();
#pragma unroll
            for (int qq = 0; qq < 2; ++qq) {
                const int c = w * 2 + qq;
                g_KhT[(size_t)(j0 + c) * N + i0 + lane] = __float2half(s_tile[c][lane]);
            }
            __syncthreads();
        }
    }
    if (tid < RPB) __stcg(&g_AF[i0 + tid], r_at);

    unsigned tgt = 0;
    grid_sync(tgt += NB);

    // ---------- phase 0b: convert fp16 -> e4m3 (linear chunks) ----------
    {
        const size_t base = (size_t)blockIdx.x * ((size_t)N * N / NB);
#pragma unroll 4
        for (int c = 0; c < 16; ++c) {
            const size_t off = base + ((size_t)c * NT + tid) * 8;
            uint4 h8 = __ldcg((const uint4*)(g_Kh + off));
            uint2 o;
            o.x = (unsigned)h2_to_e4m3x2(h8.x) | ((unsigned)h2_to_e4m3x2(h8.y) << 16);
            o.y = (unsigned)h2_to_e4m3x2(h8.z) | ((unsigned)h2_to_e4m3x2(h8.w) << 16);
            *(uint2*)(g_K8 + off) = o;
            uint4 t8 = __ldcg((const uint4*)(g_KhT + off));
            uint2 ot;
            ot.x = (unsigned)h2_to_e4m3x2(t8.x) | ((unsigned)h2_to_e4m3x2(t8.y) << 16);
            ot.y = (unsigned)h2_to_e4m3x2(t8.z) | ((unsigned)h2_to_e4m3x2(t8.w) << 16);
            *(uint2*)(g_K8T + off) = ot;
        }
    }
    grid_sync(tgt += NB);

    // ---------- fp8 iterations ----------
    for (int it = 0; it < NIT8; ++it) {
        // BF = bt^2 / (1 + K^T @ AF)
        load_vec_h(s_vh, g_AF, tid);
        __syncthreads();
        dot8<false>(g_K8T, s_vh, i0, g, q, lane, s_part);   // .cg (strip too big to share L1)
        __syncthreads();
        if (tid < RPB) {
            const float a = s_part[tid * 4] + s_part[tid * 4 + 1]
                          + s_part[tid * 4 + 2] + s_part[tid * 4 + 3];
            __stcg(&g_BF[i0 + tid], r_bt2 / (1.0f + a));
        }
        grid_sync(tgt += NB);

        // AF = AT / (1 + K @ BF)
        load_vec_h(s_vh, g_BF, tid);
        __syncthreads();
        dot8<true>(g_K8, s_vh, i0, g, q, lane, s_part);     // .ca: 128 KB strip pinned in L1
        __syncthreads();
        if (tid < RPB) {
            const float a = s_part[tid * 4] + s_part[tid * 4 + 1]
                          + s_part[tid * 4 + 2] + s_part[tid * 4 + 3];
            __stcg(&g_AF[i0 + tid], r_at / (1.0f + a));
        }
        grid_sync(tgt += NB);
    }

    // ---------- fp16 refinement iterations ----------
    for (int it = 0; it < NIT16; ++it) {
        load_vec_f(s_vec, g_AF, tid);
        __syncthreads();
        dot16(g_KhT, s_vec, i0, g, q, lane, s_part);
        __syncthreads();
        if (tid < RPB) {
            const float a = s_part[tid * 4] + s_part[tid * 4 + 1]
                          + s_part[tid * 4 + 2] + s_part[tid * 4 + 3];
            __stcg(&g_BF[i0 + tid], r_bt2 / (1.0f + a));
        }
        grid_sync(tgt += NB);

        load_vec_f(s_vec, g_BF, tid);
        __syncthreads();
        dot16(g_Kh, s_vec, i0, g, q, lane, s_part);
        __syncthreads();
        if (tid < RPB) {
            const float a = s_part[tid * 4] + s_part[tid * 4 + 1]
                          + s_part[tid * 4 + 2] + s_part[tid * 4 + 3];
            const float af = r_at / (1.0f + a);
            if (it == NIT16 - 1) s_af[tid] = af;            // last phase: keep local only
            else                 __stcg(&g_AF[i0 + tid], af);
        }
        if (it != NIT16 - 1) grid_sync(tgt += NB);
        else                 __syncthreads();               // own-block AF + already-synced BF suffice
    }

    // ---------- output: C[i][j] = AF_i * k_ij^2 * BF_j  (fp32 k for accuracy) ----------
    load_vec_f(s_vec, g_BF, tid);
    __syncthreads();

    const float af = s_af[w];                               // warp w -> row i0 + w
    const float4* sv4 = (const float4*)s_vec;
#pragma unroll 4
    for (int s = 0; s < 32; ++s) {
        const int j = s * 128 + lane * 4;
        const size_t off = (size_t)(i0 + w) * N + j;
        const float4 kv = __ldcs((const float4*)(k + off));
        const float4 bv = sv4[j >> 2];
        float4 c4;
        c4.x = af * kv.x * kv.x * bv.x;
        c4.y = af * kv.y * kv.y * bv.y;
        c4.z = af * kv.z * kv.z * bv.z;
        c4.w = af * kv.w * kv.w * bv.w;
        *(float4*)(C + off) = c4;
    }
}

extern "C" void kernel_launch(void* const* d_in, const int* in_sizes, int n_in,
                              void* d_out, int out_size) {
    const float* AT = (const float*)d_in[0];
    const float* k  = (const float*)d_in[1];
    const float* bt = (const float*)d_in[2];
    float* C = (float*)d_out;

    reset_bar_kernel<<<1, 1>>>();
    competitive_kernel<<<NB, NT>>>(AT, k, bt, C);
}

// round 4
// speedup vs baseline: 2.9251x; 1.1829x over previous
#include <cuda_runtime.h>
#include <cuda_fp16.h>

#define N       4096
#define NB      128     // persistent blocks, 1/SM, co-resident wave 1
#define NT      1024
#define RPB     32      // rows per block
#define NIT8    26      // fp8 (e4m3) iterations
#define NIT16   6       // fp16 refinement iterations

// dynamic SMEM layout
#define SM_STRIP   (RPB * N)                 // 131072 B : K^T strip, e4m3
#define SM_VEC     (N * 4)                   // 16384 B  : fp32 vector
#define SM_VH      (N * 2)                   // 8192 B   : fp16 vector
#define SM_PART    (RPB * 4 * 4)             // 512 B
#define SM_AF      (RPB * 4)                 // 128 B
#define SMEM_DYN   (SM_STRIP + SM_VEC + SM_VH + SM_PART + SM_AF)

// ---- persistent device scratch ----
__device__ __align__(16) __half        g_Kh [(size_t)N * N];   // K fp16 row-major (32 MB)
__device__ __align__(16) __half        g_KhT[(size_t)N * N];   // K^T fp16         (32 MB)
__device__ __align__(16) unsigned char g_K8 [(size_t)N * N];   // K e4m3           (16 MB)
__device__ __align__(16) float g_AF[N];
__device__ __align__(16) float g_BF[N];
__device__ unsigned int g_bar;

__global__ void reset_bar_kernel() { g_bar = 0u; }

// fence-free grid barrier: release-red arrive + L2 poll (no CCTL.IVALL)
__device__ __forceinline__ void grid_sync(unsigned target) {
    __syncthreads();
    if (threadIdx.x == 0) {
        asm volatile("red.release.gpu.global.add.u32 [%0], %1;"
                     :: "l"(&g_bar), "r"(1u) : "memory");
        unsigned v;
        do {
            asm volatile("ld.global.cg.u32 %0, [%1];" : "=r"(v) : "l"(&g_bar) : "memory");
        } while (v < target);
    }
    __syncthreads();
}

// ---- fp8 helpers ----
__device__ __forceinline__ unsigned h2_to_e4m3x2(unsigned h2bits) {
    unsigned short r;
    asm("cvt.rn.satfinite.e4m3x2.f16x2 %0, %1;" : "=h"(r) : "r"(h2bits));
    return (unsigned)r;
}
__device__ __forceinline__ __half2 e4m3x2_to_h2(unsigned short u) {
    unsigned r;
    asm("cvt.rn.f16x2.e4m3x2 %0, %1;" : "=r"(r) : "h"(u));
    return *reinterpret_cast<__half2*>(&r);
}

__device__ __forceinline__ void load_vec_f(float* s_vec, const float* g_src, int tid) {
    ((float4*)s_vec)[tid] = __ldcg((const float4*)g_src + tid);
}
__device__ __forceinline__ void load_vec_h(__half2* s_vh, const float* g_src, int tid) {
    float4 v = __ldcg((const float4*)g_src + tid);
    s_vh[2 * tid]     = __floats2half2_rn(v.x, v.y);
    s_vh[2 * tid + 1] = __floats2half2_rn(v.z, v.w);
}

// core fp8 dot on 4 rows x 1024 cols given a row base pointer with stride N
__device__ __forceinline__ void dot8_body(const unsigned char* __restrict__ Mp, bool glob,
                                          const uint4* __restrict__ vh4, int lane,
                                          float acc[4])
{
#pragma unroll
    for (int s = 0; s < 2; ++s) {
        const int e0 = (s << 9) + (lane << 4);               // 16 fp8 per lane per step
        uint4 va = vh4[(e0 >> 3)];
        uint4 vb = vh4[(e0 >> 3) + 1];
        const __half2* vha = (const __half2*)&va;
        const __half2* vhb = (const __half2*)&vb;
#pragma unroll
        for (int r = 0; r < 4; ++r) {
            const uint4* p = (const uint4*)(Mp + (size_t)r * N + e0);
            uint4 kd = glob ? __ldcg(p) : *p;                // LDS when SMEM provenance
            __half2 a2 = __floats2half2_rn(0.f, 0.f);
            a2 = __hfma2(e4m3x2_to_h2((unsigned short)kd.x),         vha[0], a2);
            a2 = __hfma2(e4m3x2_to_h2((unsigned short)(kd.x >> 16)), vha[1], a2);
            a2 = __hfma2(e4m3x2_to_h2((unsigned short)kd.y),         vha[2], a2);
            a2 = __hfma2(e4m3x2_to_h2((unsigned short)(kd.y >> 16)), vha[3], a2);
            a2 = __hfma2(e4m3x2_to_h2((unsigned short)kd.z),         vhb[0], a2);
            a2 = __hfma2(e4m3x2_to_h2((unsigned short)(kd.z >> 16)), vhb[1], a2);
            a2 = __hfma2(e4m3x2_to_h2((unsigned short)kd.w),         vhb[2], a2);
            a2 = __hfma2(e4m3x2_to_h2((unsigned short)(kd.w >> 16)), vhb[3], a2);
            float2 f = __half22float2(a2);
            acc[r] += f.x + f.y;
        }
    }
}

__device__ __forceinline__ void warp_reduce_part(float acc[4], int r0, int q, int lane,
                                                 float* __restrict__ s_part)
{
#pragma unroll
    for (int r = 0; r < 4; ++r) {
        float a = acc[r];
#pragma unroll
        for (int off = 16; off; off >>= 1) a += __shfl_xor_sync(0xffffffffu, a, off);
        if (lane == 0) s_part[((r0 + r) << 2) + q] = a;
    }
}

// fp16 strip dot (fp32 vector + fp32 accum), rows from L2
__device__ __forceinline__ void dot16(const __half* __restrict__ M,
                                      const float*  __restrict__ s_vec,
                                      int i0, int g, int q, int lane,
                                      float* __restrict__ s_part)
{
    const int c0 = q << 10;
    const int r0 = g << 2;
    const __half* Mp = M + (size_t)(i0 + r0) * N + c0;
    const float4* sv4 = (const float4*)(s_vec + c0);

    float acc[4] = {0.f, 0.f, 0.f, 0.f};
#pragma unroll
    for (int s = 0; s < 4; ++s) {
        const int i = (s << 8) + (lane << 3);
        const float4 v0 = sv4[(i >> 2)];
        const float4 v1 = sv4[(i >> 2) + 1];
#pragma unroll
        for (int r = 0; r < 4; ++r) {
            const float4 kr = __ldcg((const float4*)(Mp + (size_t)r * N + i));
            const __half2* h = (const __half2*)&kr;
            const float2 f0 = __half22float2(h[0]);
            const float2 f1 = __half22float2(h[1]);
            const float2 f2 = __half22float2(h[2]);
            const float2 f3 = __half22float2(h[3]);
            acc[r] += f0.x * v0.x + f0.y * v0.y + f1.x * v0.z + f1.y * v0.w
                    + f2.x * v1.x + f2.y * v1.y + f3.x * v1.z + f3.y * v1.w;
        }
    }
    warp_reduce_part(acc, r0, q, lane, s_part);
}

__global__ void __launch_bounds__(NT, 1)
competitive_kernel(const float* __restrict__ AT, const float* __restrict__ k,
                   const float* __restrict__ bt, float* __restrict__ C)
{
    extern __shared__ char s_dyn[];
    unsigned char* s_strip = (unsigned char*)s_dyn;                    // 128 KB K^T fp8 strip
    float*   s_vec  = (float*)  (s_dyn + SM_STRIP);                    // 16 KB
    __half2* s_vh   = (__half2*)(s_dyn + SM_STRIP + SM_VEC);           // 8 KB
    float*   s_part = (float*)  (s_dyn + SM_STRIP + SM_VEC + SM_VH);
    float*   s_af   = (float*)  (s_dyn + SM_STRIP + SM_VEC + SM_VH + SM_PART);

    const int tid  = threadIdx.x;
    const int w    = tid >> 5;
    const int lane = tid & 31;
    const int g    = w >> 2;                 // row group 0..7
    const int q    = w & 3;                  // column quarter 0..3
    const int i0   = blockIdx.x * RPB;

    float r_at = 0.f, r_bt2 = 0.f;
    if (tid < RPB) {
        r_at = AT[i0 + tid];
        float b = bt[i0 + tid];
        r_bt2 = b * b;
    }

    // ---------- setup (fused): Kh = fp16(k*k), K8 = fp8(k*k), KhT = transpose ----------
    {
        float (*s_tile)[33] = (float(*)[33])s_vec;      // 64*33*4 = 8.4 KB
        for (int t = 0; t < N / 64; ++t) {
            const int j0 = t * 64;
            const size_t roff = (size_t)(i0 + w) * N + j0;
            float2 v = __ldcs((const float2*)(k + roff) + lane);
            v.x *= v.x; v.y *= v.y;
            const __half2 h2 = __floats2half2_rn(v.x, v.y);
            *(__half2*)(g_Kh + roff + lane * 2) = h2;
            *(unsigned short*)(g_K8 + roff + lane * 2) =
                (unsigned short)h2_to_e4m3x2(*(const unsigned*)&h2);
            s_tile[lane * 2    ][w] = v.x;
            s_tile[lane * 2 + 1][w] = v.y;
            __syncthreads();
#pragma unroll
            for (int qq = 0; qq < 2; ++qq) {
                const int c = w * 2 + qq;
                g_KhT[(size_t)(j0 + c) * N + i0 + lane] = __float2half(s_tile[c][lane]);
            }
            __syncthreads();
        }
    }
    if (tid < RPB) __stcg(&g_AF[i0 + tid], r_at);

    unsigned tgt = 0;
    grid_sync(tgt += NB);

    // ---------- gather this block's K^T strip into SMEM as fp8 ----------
    {
        const uint4* src = (const uint4*)(g_KhT + (size_t)i0 * N);   // 32 rows x 4096 halfs
        uint2* dst = (uint2*)s_strip;
#pragma unroll 4
        for (int s = 0; s < 16; ++s) {
            const int idx = s * NT + tid;                 // 16384 uint4 chunks (8 halfs)
            uint4 h8 = __ldcg(src + idx);
            uint2 o;
            o.x = h2_to_e4m3x2(h8.x) | (h2_to_e4m3x2(h8.y) << 16);
            o.y = h2_to_e4m3x2(h8.z) | (h2_to_e4m3x2(h8.w) << 16);
            dst[idx] = o;
        }
    }
    __syncthreads();

    // ---------- fp8 iterations ----------
    for (int it = 0; it < NIT8; ++it) {
        // BF = bt^2 / (1 + K^T @ AF)  -- strip from SMEM, zero global loads
        load_vec_h(s_vh, g_AF, tid);
        __syncthreads();
        {
            float acc[4] = {0.f, 0.f, 0.f, 0.f};
            const unsigned char* Mp = s_strip + (size_t)(g << 2) * N + (q << 10);
            const uint4* vh4 = (const uint4*)((const char*)s_vh + (q << 11));
            dot8_body(Mp, false, vh4, lane, acc);
            warp_reduce_part(acc, g << 2, q, lane, s_part);
        }
        __syncthreads();
        if (tid < RPB) {
            const float a = s_part[tid * 4] + s_part[tid * 4 + 1]
                          + s_part[tid * 4 + 2] + s_part[tid * 4 + 3];
            __stcg(&g_BF[i0 + tid], r_bt2 / (1.0f + a));
        }
        grid_sync(tgt += NB);

        // AF = AT / (1 + K @ BF)  -- K strip from L2 (written by this SM, stays hot)
        load_vec_h(s_vh, g_BF, tid);
        __syncthreads();
        {
            float acc[4] = {0.f, 0.f, 0.f, 0.f};
            const unsigned char* Mp = g_K8 + (size_t)(i0 + (g << 2)) * N + (q << 10);
            const uint4* vh4 = (const uint4*)((const char*)s_vh + (q << 11));
            dot8_body(Mp, true, vh4, lane, acc);
            warp_reduce_part(acc, g << 2, q, lane, s_part);
        }
        __syncthreads();
        if (tid < RPB) {
            const float a = s_part[tid * 4] + s_part[tid * 4 + 1]
                          + s_part[tid * 4 + 2] + s_part[tid * 4 + 3];
            __stcg(&g_AF[i0 + tid], r_at / (1.0f + a));
        }
        grid_sync(tgt += NB);
    }

    // ---------- fp16 refinement iterations ----------
    for (int it = 0; it < NIT16; ++it) {
        load_vec_f(s_vec, g_AF, tid);
        __syncthreads();
        dot16(g_KhT, s_vec, i0, g, q, lane, s_part);
        __syncthreads();
        if (tid < RPB) {
            const float a = s_part[tid * 4] + s_part[tid * 4 + 1]
                          + s_part[tid * 4 + 2] + s_part[tid * 4 + 3];
            __stcg(&g_BF[i0 + tid], r_bt2 / (1.0f + a));
        }
        grid_sync(tgt += NB);

        load_vec_f(s_vec, g_BF, tid);
        __syncthreads();
        dot16(g_Kh, s_vec, i0, g, q, lane, s_part);
        __syncthreads();
        if (tid < RPB) {
            const float a = s_part[tid * 4] + s_part[tid * 4 + 1]
                          + s_part[tid * 4 + 2] + s_part[tid * 4 + 3];
            const float af = r_at / (1.0f + a);
            if (it == NIT16 - 1) s_af[tid] = af;           // final: keep local
            else                 __stcg(&g_AF[i0 + tid], af);
        }
        if (it != NIT16 - 1) grid_sync(tgt += NB);
        else                 __syncthreads();
    }

    // ---------- output: C[i][j] = AF_i * k_ij^2 * BF_j  (fp32 k) ----------
    load_vec_f(s_vec, g_BF, tid);
    __syncthreads();

    const float af = s_af[w];                              // warp w -> row i0 + w
    const float4* sv4 = (const float4*)s_vec;
#pragma unroll 4
    for (int s = 0; s < 32; ++s) {
        const int j = s * 128 + lane * 4;
        const size_t off = (size_t)(i0 + w) * N + j;
        const float4 kv = __ldcs((const float4*)(k + off));
        const float4 bv = sv4[j >> 2];
        float4 c4;
        c4.x = af * kv.x * kv.x * bv.x;
        c4.y = af * kv.y * kv.y * bv.y;
        c4.z = af * kv.z * kv.z * bv.z;
        c4.w = af * kv.w * kv.w * bv.w;
        *(float4*)(C + off) = c4;
    }
}

extern "C" void kernel_launch(void* const* d_in, const int* in_sizes, int n_in,
                              void* d_out, int out_size) {
    const float* AT = (const float*)d_in[0];
    const float* k  = (const float*)d_in[1];
    const float* bt = (const float*)d_in[2];
    float* C = (float*)d_out;

    cudaFuncSetAttribute(competitive_kernel,
                         cudaFuncAttributeMaxDynamicSharedMemorySize, SMEM_DYN);
    reset_bar_kernel<<<1, 1>>>();
    competitive_kernel<<<NB, NT, SMEM_DYN>>>(AT, k, bt, C);
}